// round 5
// baseline (speedup 1.0000x reference)
#include <cuda_runtime.h>
#include <cstdint>

// Problem constants (match reference)
#define B      32
#define TMAX   512
#define D      384
#define MAXDUR 8
#define TOUT   (TMAX * (MAXDUR - 1))   // 3584
#define VEC    (D / 4)                 // 96 float4 per row
#define NTHR   512                     // 16 warps
#define ROWS_PER_CTA 32                // 16 warps x 2 frames
#define CTAS_PER_B   (TOUT / ROWS_PER_CTA)   // 112
#define NCTAS  (B * CTAS_PER_B)        // 3584

// ---------------------------------------------------------------------------
// Fused kernel, scan amortized over 32 output rows per CTA.
// 512 threads: thread t owns scan element t (1 elem/thread, shfl warp scan +
// 16-entry cross-warp scan). Each of the 16 warps then produces 2 output
// frames: f_base + wid and f_base + wid + 16. 6 independent float4 loads +
// 6 streaming stores per thread (MLP 6).
// ---------------------------------------------------------------------------
__global__ void __launch_bounds__(NTHR) lenreg_fused_kernel(
    const float4* __restrict__ xs,     // [B, TMAX, VEC]
    const int*    __restrict__ ds,     // [B, TMAX]
    const int*    __restrict__ ilens,  // [B]
    float4*       __restrict__ out)    // [B, TOUT, VEC]
{
    const int cta    = blockIdx.x;
    const int b      = cta / CTAS_PER_B;              // mul-shift
    const int f_base = (cta - b * CTAS_PER_B) * ROWS_PER_CTA;

    const int t    = threadIdx.x;     // 0..511
    const int lane = t & 31;
    const int wid  = t >> 5;          // 0..15

    __shared__ int s_cum[TMAX];       // inclusive cumsum of masked durations
    __shared__ int s_wsum[16];

    const int L = ilens[b];

    // --- block scan: thread t owns element t ------------------------------
    int d = (t < L) ? __ldg(ds + b * TMAX + t) : 0;

    int cum = d;
    #pragma unroll
    for (int off = 1; off < 32; off <<= 1) {
        int v = __shfl_up_sync(0xffffffffu, cum, off);
        if (lane >= off) cum += v;
    }
    if (lane == 31) s_wsum[wid] = cum;
    __syncthreads();

    if (wid == 0 && lane < 16) {
        int v = s_wsum[lane];
        #pragma unroll
        for (int off = 1; off < 16; off <<= 1) {
            int u = __shfl_up_sync(0x0000ffffu, v, off);
            if (lane >= off) v += u;
        }
        s_wsum[lane] = v;
    }
    __syncthreads();

    cum += (wid > 0) ? s_wsum[wid - 1] : 0;
    int total = s_wsum[15];

    if (total == 0) {
        // all-zero fallback: d = mask -> cum[t] = min(t+1, L)
        cum   = (t < L) ? (t + 1) : L;
        total = L;                         // L >= 1 guaranteed
    }
    s_cum[t] = cum;
    __syncthreads();

    // --- per-warp: 2 frames, binary search + gather ------------------------
    const int f0 = f_base + wid;
    const int f1 = f_base + wid + 16;

    // searchsorted(cum, f, side='right'); 10 steps for range [0, 512]
    int lo0 = 0, hi0 = TMAX;
    int lo1 = 0, hi1 = TMAX;
    #pragma unroll
    for (int step = 0; step < 10; ++step) {
        int m0 = (lo0 + hi0) >> 1;
        int m1 = (lo1 + hi1) >> 1;
        if (s_cum[m0] <= f0) lo0 = m0 + 1; else hi0 = m0;
        if (s_cum[m1] <= f1) lo1 = m1 + 1; else hi1 = m1;
    }
    const int i0 = (lo0 < TMAX - 1) ? lo0 : (TMAX - 1);
    const int i1 = (lo1 < TMAX - 1) ? lo1 : (TMAX - 1);

    const float4 z = make_float4(0.f, 0.f, 0.f, 0.f);
    const float4* xb = xs + (long)b * TMAX * VEC;

    const bool v0 = (f0 < total);
    const bool v1 = (f1 < total);
    const float4* s0 = xb + (long)i0 * VEC;
    const float4* s1 = xb + (long)i1 * VEC;

    // 6 independent loads (predicated), then 6 streaming stores
    float4 a0 = z, a1 = z, a2 = z, b0 = z, b1 = z, b2 = z;
    if (v0) {
        a0 = __ldg(s0 + lane);
        a1 = __ldg(s0 + lane + 32);
        a2 = __ldg(s0 + lane + 64);
    }
    if (v1) {
        b0 = __ldg(s1 + lane);
        b1 = __ldg(s1 + lane + 32);
        b2 = __ldg(s1 + lane + 64);
    }

    float4* d0p = out + ((long)b * TOUT + f0) * VEC;
    float4* d1p = out + ((long)b * TOUT + f1) * VEC;
    __stcs(d0p + lane,      a0);
    __stcs(d0p + lane + 32, a1);
    __stcs(d0p + lane + 64, a2);
    __stcs(d1p + lane,      b0);
    __stcs(d1p + lane + 32, b1);
    __stcs(d1p + lane + 64, b2);
}

extern "C" void kernel_launch(void* const* d_in, const int* in_sizes, int n_in,
                              void* d_out, int out_size)
{
    const float* xs    = (const float*)d_in[0];  // [B, TMAX, D] fp32
    const int*   ds    = (const int*)  d_in[1];  // [B, TMAX] int32
    const int*   ilens = (const int*)  d_in[2];  // [B] int32
    float*       out   = (float*)d_out;          // [B, TOUT, D] fp32

    lenreg_fused_kernel<<<NCTAS, NTHR>>>(
        (const float4*)xs, ds, ilens, (float4*)out);
}